// round 1
// baseline (speedup 1.0000x reference)
#include <cuda_runtime.h>
#include <stdint.h>

#define N_NODES 4096
#define IN_F    512
#define HEADS   8
#define HPH     8
#define HID     64
#define CLS     16
#define MAXDEG  128

// ---------------- scratch (static device globals; no allocation) ----------------
__device__ float g_g1[N_NODES * HID];      // layer-1 projection [N,64]
__device__ float g_sl1[N_NODES * HEADS];
__device__ float g_sr1[N_NODES * HEADS];
__device__ float g_h[N_NODES * HID];       // elu(layer-1 out)
__device__ float g_g2[N_NODES * CLS];      // layer-2 projection
__device__ float g_sl2[N_NODES];
__device__ float g_sr2[N_NODES];
__device__ int   g_cols[N_NODES * MAXDEG]; // ELL neighbor lists
__device__ int   g_deg[N_NODES];

// ---------------- ELL build: one block per row, deterministic ordered scan ------
// dtype probe (uniform across all blocks):
//   byte[3]==0x3F  -> float32 (adj[0,0]=1.0f, bytes 00 00 80 3F)
//   byte[4097]==1  -> bool/uint8 (adj[1,1] diagonal byte; int32/float have 0 there)
//   else           -> int32
__global__ void build_ell(const unsigned char* __restrict__ adj) {
    const int i = blockIdx.x;
    const int t = threadIdx.x; // 256 threads

    int dt;
    if (adj[3] == 0x3Fu)        dt = 1;      // float32
    else if (adj[4097] == 1u)   dt = 0;      // bool / uint8
    else                        dt = 2;      // int32

    // pass 1: count nonzeros in this thread's contiguous 16-element chunk
    int cnt = 0;
    if (dt == 0) {
        const uint32_t* p = (const uint32_t*)(adj + (size_t)i * N_NODES) + t * 4;
        #pragma unroll
        for (int k = 0; k < 4; k++) {
            uint32_t v = p[k];
            if (v) {
                cnt += ((v       & 0xFFu) != 0) + (((v >> 8)  & 0xFFu) != 0)
                     + (((v >> 16) & 0xFFu) != 0) + (((v >> 24) & 0xFFu) != 0);
            }
        }
    } else if (dt == 1) {
        const float4* p = (const float4*)(adj) + (size_t)i * (N_NODES / 4) + t * 4;
        #pragma unroll
        for (int k = 0; k < 4; k++) {
            float4 v = p[k];
            cnt += (v.x != 0.f) + (v.y != 0.f) + (v.z != 0.f) + (v.w != 0.f);
        }
    } else {
        const int4* p = (const int4*)(adj) + (size_t)i * (N_NODES / 4) + t * 4;
        #pragma unroll
        for (int k = 0; k < 4; k++) {
            int4 v = p[k];
            cnt += (v.x != 0) + (v.y != 0) + (v.z != 0) + (v.w != 0);
        }
    }

    // block-wide inclusive scan (Hillis-Steele, 256 lanes)
    __shared__ int scan[256];
    scan[t] = cnt;
    __syncthreads();
    #pragma unroll
    for (int off = 1; off < 256; off <<= 1) {
        int v   = scan[t];
        int add = (t >= off) ? scan[t - off] : 0;
        __syncthreads();
        scan[t] = v + add;
        __syncthreads();
    }
    int pos = scan[t] - cnt;       // exclusive prefix
    const int total = scan[255];

    // pass 2: re-read chunk (L1-hot), write neighbor indices in order
    const int j0 = t * 16;
    int* dst = &g_cols[(size_t)i * MAXDEG];
    if (dt == 0) {
        const uint32_t* p = (const uint32_t*)(adj + (size_t)i * N_NODES) + t * 4;
        #pragma unroll
        for (int k = 0; k < 4; k++) {
            uint32_t v = p[k];
            #pragma unroll
            for (int b = 0; b < 4; b++) {
                if ((v >> (8 * b)) & 0xFFu) { if (pos < MAXDEG) dst[pos] = j0 + k * 4 + b; pos++; }
            }
        }
    } else if (dt == 1) {
        const float* p = (const float*)(adj) + (size_t)i * N_NODES + j0;
        #pragma unroll
        for (int k = 0; k < 16; k++) {
            if (p[k] != 0.f) { if (pos < MAXDEG) dst[pos] = j0 + k; pos++; }
        }
    } else {
        const int* p = (const int*)(adj) + (size_t)i * N_NODES + j0;
        #pragma unroll
        for (int k = 0; k < 16; k++) {
            if (p[k] != 0) { if (pos < MAXDEG) dst[pos] = j0 + k; pos++; }
        }
    }
    if (t == 0) g_deg[i] = min(total, MAXDEG);
}

// ---------------- GEMM1: g1[N,64] = x[N,512] @ W1[512,64] ----------------------
// BM=32, BN=64, BK=32, 128 threads, 4x4 register tiles. 128 blocks.
__global__ void gemm1(const float* __restrict__ x, const float* __restrict__ W1) {
    __shared__ float As[32][36];  // transposed: As[k][m], padded (36 % 4 == 0 keeps f4 align)
    __shared__ float Bs[32][64];
    const int tid = threadIdx.x;
    const int m0  = blockIdx.x * 32;
    const int tx  = tid & 15;   // 16 col-tiles * 4 = 64
    const int ty  = tid >> 4;   // 8 row-tiles  * 4 = 32

    float acc[4][4] = {};

    for (int k0 = 0; k0 < IN_F; k0 += 32) {
        // load A tile (32 rows x 32 k): 256 float4 / 128 threads
        #pragma unroll
        for (int it = 0; it < 2; it++) {
            int idx = it * 128 + tid;
            int r = idx >> 3, c4 = idx & 7;
            float4 v = *(const float4*)&x[(size_t)(m0 + r) * IN_F + k0 + c4 * 4];
            As[c4 * 4 + 0][r] = v.x;
            As[c4 * 4 + 1][r] = v.y;
            As[c4 * 4 + 2][r] = v.z;
            As[c4 * 4 + 3][r] = v.w;
        }
        // load B tile (32 k x 64 cols): 512 float4 / 128 threads
        #pragma unroll
        for (int it = 0; it < 4; it++) {
            int idx = it * 128 + tid;
            int kk = idx >> 4, c4 = idx & 15;
            *(float4*)&Bs[kk][c4 * 4] = *(const float4*)&W1[(size_t)(k0 + kk) * HID + c4 * 4];
        }
        __syncthreads();
        #pragma unroll
        for (int kk = 0; kk < 32; kk++) {
            float4 a = *(const float4*)&As[kk][ty * 4];
            float4 b = *(const float4*)&Bs[kk][tx * 4];
            float av[4] = {a.x, a.y, a.z, a.w};
            float bv[4] = {b.x, b.y, b.z, b.w};
            #pragma unroll
            for (int r = 0; r < 4; r++)
                #pragma unroll
                for (int c = 0; c < 4; c++)
                    acc[r][c] = fmaf(av[r], bv[c], acc[r][c]);
        }
        __syncthreads();
    }
    #pragma unroll
    for (int r = 0; r < 4; r++) {
        float4 v = make_float4(acc[r][0], acc[r][1], acc[r][2], acc[r][3]);
        *(float4*)&g_g1[(size_t)(m0 + ty * 4 + r) * HID + tx * 4] = v;
    }
}

// ---------------- per-(node,head) attention scores sl/sr (layer 1) -------------
__global__ void slsr1(const float* __restrict__ a1l, const float* __restrict__ a1r) {
    int idx = blockIdx.x * blockDim.x + threadIdx.x; // N*HEADS = 32768
    if (idx >= N_NODES * HEADS) return;
    int i = idx >> 3, h = idx & 7;
    const float* g = &g_g1[(size_t)i * HID + h * HPH];
    const float* al = &a1l[h * HPH];
    const float* ar = &a1r[h * HPH];
    float sl = 0.f, sr = 0.f;
    #pragma unroll
    for (int d = 0; d < HPH; d++) { sl = fmaf(g[d], al[d], sl); sr = fmaf(g[d], ar[d], sr); }
    g_sl1[idx] = sl;
    g_sr1[idx] = sr;
}

// ---------------- layer-1 attention + aggregation + ELU ------------------------
// one block (64 threads) per row i; thread t owns feature t = h*8+d
__global__ void attn1() {
    const int i = blockIdx.x;
    const int t = threadIdx.x;
    __shared__ int   cols[MAXDEG];
    __shared__ float w[MAXDEG][HEADS];
    __shared__ float sinv[HEADS];

    const int deg = g_deg[i];
    for (int n = t; n < deg; n += 64) cols[n] = g_cols[(size_t)i * MAXDEG + n];
    __syncthreads();

    // scores: e = leaky_relu(sl[i,h] + sr[j,h])
    for (int idx = t; idx < deg * HEADS; idx += 64) {
        int n = idx >> 3, h = idx & 7;
        float e = g_sl1[i * HEADS + h] + g_sr1[cols[n] * HEADS + h];
        e = (e > 0.f) ? e : 0.2f * e;
        w[n][h] = e;
    }
    __syncthreads();

    // per-head softmax (deg ~17: serial per head is cheap)
    if (t < HEADS) {
        float m = -1e30f;
        for (int n = 0; n < deg; n++) m = fmaxf(m, w[n][t]);
        float s = 0.f;
        for (int n = 0; n < deg; n++) {
            float ex = expf(w[n][t] - m);
            w[n][t] = ex;
            s += ex;
        }
        sinv[t] = 1.0f / s;
    }
    __syncthreads();

    // aggregate: out[i,h,d] = sum_n w[n][h] * g1[j, h*8+d]
    const int h = t >> 3;
    float acc = 0.f;
    for (int n = 0; n < deg; n++)
        acc = fmaf(w[n][h], g_g1[(size_t)cols[n] * HID + t], acc);
    acc *= sinv[h];
    // ELU
    acc = (acc > 0.f) ? acc : expm1f(acc);
    g_h[(size_t)i * HID + t] = acc;
}

// ---------------- GEMM2 + sl2/sr2: g2[N,16] = h[N,64] @ W2[64,16] --------------
// 16 rows per block, 256 threads (16 threads per row)
__global__ void gemm2(const float* __restrict__ W2,
                      const float* __restrict__ a2l, const float* __restrict__ a2r) {
    __shared__ float hs[16][64];
    __shared__ float w2s[64][CLS];
    const int tid  = threadIdx.x;
    const int row0 = blockIdx.x * 16;

    { int r = tid >> 4, c4 = tid & 15;
      *(float4*)&hs[r][c4 * 4] = *(const float4*)&g_h[(size_t)(row0 + r) * HID + c4 * 4]; }
    { int k = tid >> 2, c4 = tid & 3;
      *(float4*)&w2s[k][c4 * 4] = *(const float4*)&W2[(size_t)k * CLS + c4 * 4]; }
    __syncthreads();

    const int r = tid >> 4, c = tid & 15;
    float acc = 0.f;
    #pragma unroll
    for (int k = 0; k < HID; k++) acc = fmaf(hs[r][k], w2s[k][c], acc);
    g_g2[(size_t)(row0 + r) * CLS + c] = acc;

    float pl = acc * a2l[c];
    float pr = acc * a2r[c];
    #pragma unroll
    for (int off = 8; off >= 1; off >>= 1) {
        pl += __shfl_xor_sync(0xFFFFFFFFu, pl, off);
        pr += __shfl_xor_sync(0xFFFFFFFFu, pr, off);
    }
    if (c == 0) { g_sl2[row0 + r] = pl; g_sr2[row0 + r] = pr; }
}

// ---------------- layer-2 attention + aggregation (1 head, mean == identity) ---
// one warp per row
__global__ void attn2(float* __restrict__ out) {
    const int i    = blockIdx.x;
    const int lane = threadIdx.x;
    __shared__ int   cols[MAXDEG];
    __shared__ float w[MAXDEG];

    const int deg = g_deg[i];
    for (int n = lane; n < deg; n += 32) cols[n] = g_cols[(size_t)i * MAXDEG + n];
    __syncwarp();

    const float sli = g_sl2[i];
    float m = -1e30f;
    for (int n = lane; n < deg; n += 32) {
        float e = sli + g_sr2[cols[n]];
        e = (e > 0.f) ? e : 0.2f * e;
        w[n] = e;
        m = fmaxf(m, e);
    }
    #pragma unroll
    for (int off = 16; off >= 1; off >>= 1) m = fmaxf(m, __shfl_xor_sync(0xFFFFFFFFu, m, off));
    __syncwarp();

    float s = 0.f;
    for (int n = lane; n < deg; n += 32) {
        float ex = expf(w[n] - m);
        w[n] = ex;
        s += ex;
    }
    #pragma unroll
    for (int off = 16; off >= 1; off >>= 1) s += __shfl_xor_sync(0xFFFFFFFFu, s, off);
    __syncwarp();

    const float inv = 1.0f / s;
    if (lane < CLS) {
        float acc = 0.f;
        for (int n = 0; n < deg; n++)
            acc = fmaf(w[n], g_g2[(size_t)cols[n] * CLS + lane], acc);
        out[(size_t)i * CLS + lane] = acc * inv;
    }
}

// ---------------- launch ----------------
extern "C" void kernel_launch(void* const* d_in, const int* in_sizes, int n_in,
                              void* d_out, int out_size) {
    const float* x   = (const float*)d_in[0];
    const unsigned char* adj = (const unsigned char*)d_in[1];
    const float* W1  = (const float*)d_in[2];
    const float* a1l = (const float*)d_in[3];
    const float* a1r = (const float*)d_in[4];
    const float* W2  = (const float*)d_in[5];
    const float* a2l = (const float*)d_in[6];
    const float* a2r = (const float*)d_in[7];
    float* out = (float*)d_out;

    build_ell<<<N_NODES, 256>>>(adj);
    gemm1<<<N_NODES / 32, 128>>>(x, W1);
    slsr1<<<(N_NODES * HEADS + 255) / 256, 256>>>(a1l, a1r);
    attn1<<<N_NODES, 64>>>();
    gemm2<<<N_NODES / 16, 256>>>(W2, a2l, a2r);
    attn2<<<N_NODES, 32>>>(out);
}

// round 2
// speedup vs baseline: 1.5624x; 1.5624x over previous
#include <cuda_runtime.h>
#include <stdint.h>

#define N_NODES 4096
#define IN_F    512
#define HEADS   8
#define HPH     8
#define HID     64
#define CLS     16
#define MAXDEG  128

// ---------------- scratch (static device globals; no allocation) ----------------
__device__ float g_g1[N_NODES * HID];      // layer-1 projection [N,64]
__device__ float g_sl1[N_NODES * HEADS];
__device__ float g_sr1[N_NODES * HEADS];
__device__ float g_h[N_NODES * HID];       // elu(layer-1 out)
__device__ float g_g2[N_NODES * CLS];      // layer-2 projection
__device__ float g_sl2[N_NODES];
__device__ float g_sr2[N_NODES];
__device__ int   g_cols[N_NODES * MAXDEG]; // ELL neighbor lists
__device__ int   g_deg[N_NODES];

// ---------------- ELL build: one block per row, warp-shuffle scan --------------
// dtype probe (uniform across all blocks):
//   byte[3]==0x3F  -> float32 (adj[0,0]=1.0f, bytes 00 00 80 3F)
//   byte[4097]==1  -> bool/uint8 (adj[1,1] diagonal byte; int32/float have 0 there)
//   else           -> int32
__global__ void build_ell(const unsigned char* __restrict__ adj) {
    const int i    = blockIdx.x;
    const int t    = threadIdx.x;      // 256 threads, 16 elements each
    const int lane = t & 31;
    const int wid  = t >> 5;

    int dt;
    if (adj[3] == 0x3Fu)        dt = 1;      // float32
    else if (adj[4097] == 1u)   dt = 0;      // bool / uint8
    else                        dt = 2;      // int32

    // load this thread's 16-element chunk into registers + count nonzeros
    uint32_t vb[4];              // bool path: 4x u32 = 16 bytes
    float4   vf[4];              // float path: 16 floats
    int4     vi[4];              // int path: 16 ints
    int cnt = 0;
    if (dt == 0) {
        const uint4 u = *((const uint4*)(adj + (size_t)i * N_NODES) + t);
        vb[0] = u.x; vb[1] = u.y; vb[2] = u.z; vb[3] = u.w;
        #pragma unroll
        for (int k = 0; k < 4; k++) {
            uint32_t v = vb[k];
            if (v) {
                cnt += ((v       & 0xFFu) != 0) + (((v >> 8)  & 0xFFu) != 0)
                     + (((v >> 16) & 0xFFu) != 0) + (((v >> 24) & 0xFFu) != 0);
            }
        }
    } else if (dt == 1) {
        const float4* p = (const float4*)(adj) + (size_t)i * (N_NODES / 4) + t * 4;
        #pragma unroll
        for (int k = 0; k < 4; k++) {
            vf[k] = p[k];
            cnt += (vf[k].x != 0.f) + (vf[k].y != 0.f) + (vf[k].z != 0.f) + (vf[k].w != 0.f);
        }
    } else {
        const int4* p = (const int4*)(adj) + (size_t)i * (N_NODES / 4) + t * 4;
        #pragma unroll
        for (int k = 0; k < 4; k++) {
            vi[k] = p[k];
            cnt += (vi[k].x != 0) + (vi[k].y != 0) + (vi[k].z != 0) + (vi[k].w != 0);
        }
    }

    // warp inclusive scan
    int incl = cnt;
    #pragma unroll
    for (int off = 1; off < 32; off <<= 1) {
        int v = __shfl_up_sync(0xFFFFFFFFu, incl, off);
        if (lane >= off) incl += v;
    }

    __shared__ int wsum[8];
    __shared__ int woff[9];
    if (lane == 31) wsum[wid] = incl;
    __syncthreads();
    if (t == 0) {
        int s = 0;
        #pragma unroll
        for (int w = 0; w < 8; w++) { woff[w] = s; s += wsum[w]; }
        woff[8] = s;
    }
    __syncthreads();

    int pos = woff[wid] + (incl - cnt);   // global exclusive prefix
    const int total = woff[8];

    // write neighbor indices from registers, in order
    const int j0 = t * 16;
    int* dst = &g_cols[(size_t)i * MAXDEG];
    if (dt == 0) {
        #pragma unroll
        for (int k = 0; k < 4; k++) {
            uint32_t v = vb[k];
            #pragma unroll
            for (int b = 0; b < 4; b++) {
                if ((v >> (8 * b)) & 0xFFu) { if (pos < MAXDEG) dst[pos] = j0 + k * 4 + b; pos++; }
            }
        }
    } else if (dt == 1) {
        #pragma unroll
        for (int k = 0; k < 4; k++) {
            float e[4] = {vf[k].x, vf[k].y, vf[k].z, vf[k].w};
            #pragma unroll
            for (int b = 0; b < 4; b++)
                if (e[b] != 0.f) { if (pos < MAXDEG) dst[pos] = j0 + k * 4 + b; pos++; }
        }
    } else {
        #pragma unroll
        for (int k = 0; k < 4; k++) {
            int e[4] = {vi[k].x, vi[k].y, vi[k].z, vi[k].w};
            #pragma unroll
            for (int b = 0; b < 4; b++)
                if (e[b] != 0) { if (pos < MAXDEG) dst[pos] = j0 + k * 4 + b; pos++; }
        }
    }
    if (t == 0) g_deg[i] = min(total, MAXDEG);
}

// ---------------- GEMM1 + fused sl/sr: g1[N,64] = x[N,512] @ W1[512,64] --------
// BM=32, BN=64, BK=32, 128 threads, 4x4 register tiles. 128 blocks.
// Epilogue computes sl1/sr1 per (row, head) from the accumulators.
__global__ void gemm1(const float* __restrict__ x, const float* __restrict__ W1,
                      const float* __restrict__ a1l, const float* __restrict__ a1r) {
    __shared__ float As[32][36];  // transposed: As[k][m]
    __shared__ float Bs[32][64];
    __shared__ float al[HID], ar[HID];
    const int tid = threadIdx.x;
    const int m0  = blockIdx.x * 32;
    const int tx  = tid & 15;   // col tile of 4:  cols tx*4..tx*4+3
    const int ty  = tid >> 4;   // row tile of 4:  rows ty*4..ty*4+3

    if (tid < HID) { al[tid] = a1l[tid]; ar[tid] = a1r[tid]; }

    float acc[4][4] = {};

    for (int k0 = 0; k0 < IN_F; k0 += 32) {
        #pragma unroll
        for (int it = 0; it < 2; it++) {
            int idx = it * 128 + tid;
            int r = idx >> 3, c4 = idx & 7;
            float4 v = *(const float4*)&x[(size_t)(m0 + r) * IN_F + k0 + c4 * 4];
            As[c4 * 4 + 0][r] = v.x;
            As[c4 * 4 + 1][r] = v.y;
            As[c4 * 4 + 2][r] = v.z;
            As[c4 * 4 + 3][r] = v.w;
        }
        #pragma unroll
        for (int it = 0; it < 4; it++) {
            int idx = it * 128 + tid;
            int kk = idx >> 4, c4 = idx & 15;
            *(float4*)&Bs[kk][c4 * 4] = *(const float4*)&W1[(size_t)(k0 + kk) * HID + c4 * 4];
        }
        __syncthreads();
        #pragma unroll
        for (int kk = 0; kk < 32; kk++) {
            float4 a = *(const float4*)&As[kk][ty * 4];
            float4 b = *(const float4*)&Bs[kk][tx * 4];
            float av[4] = {a.x, a.y, a.z, a.w};
            float bv[4] = {b.x, b.y, b.z, b.w};
            #pragma unroll
            for (int r = 0; r < 4; r++)
                #pragma unroll
                for (int c = 0; c < 4; c++)
                    acc[r][c] = fmaf(av[r], bv[c], acc[r][c]);
        }
        __syncthreads();
    }

    // store g1 + fused sl/sr epilogue. head of this col tile = tx>>1 (8 cols/head).
    const int head = tx >> 1;
    #pragma unroll
    for (int r = 0; r < 4; r++) {
        const int row = m0 + ty * 4 + r;
        *(float4*)&g_g1[(size_t)row * HID + tx * 4] =
            make_float4(acc[r][0], acc[r][1], acc[r][2], acc[r][3]);

        float pl = 0.f, pr = 0.f;
        #pragma unroll
        for (int c = 0; c < 4; c++) {
            pl = fmaf(acc[r][c], al[tx * 4 + c], pl);
            pr = fmaf(acc[r][c], ar[tx * 4 + c], pr);
        }
        pl += __shfl_xor_sync(0xFFFFFFFFu, pl, 1);   // combine the two col-tiles of a head
        pr += __shfl_xor_sync(0xFFFFFFFFu, pr, 1);
        if (!(tx & 1)) {
            g_sl1[row * HEADS + head] = pl;
            g_sr1[row * HEADS + head] = pr;
        }
    }
}

// ---------------- layer-1 attention + aggregation + ELU ------------------------
// one block (64 threads) per row i; thread t owns feature t = h*8+d
__global__ void attn1() {
    const int i = blockIdx.x;
    const int t = threadIdx.x;
    __shared__ int   cols[MAXDEG];
    __shared__ float w[MAXDEG][HEADS];
    __shared__ float sinv[HEADS];

    const int deg = g_deg[i];
    for (int n = t; n < deg; n += 64) cols[n] = g_cols[(size_t)i * MAXDEG + n];
    __syncthreads();

    // scores: e = leaky_relu(sl[i,h] + sr[j,h])
    for (int idx = t; idx < deg * HEADS; idx += 64) {
        int n = idx >> 3, h = idx & 7;
        float e = g_sl1[i * HEADS + h] + g_sr1[cols[n] * HEADS + h];
        w[n][h] = fmaxf(e, 0.2f * e);
    }
    __syncthreads();

    // per-head softmax (deg ~17)
    if (t < HEADS) {
        float m = -1e30f;
        for (int n = 0; n < deg; n++) m = fmaxf(m, w[n][t]);
        float s = 0.f;
        for (int n = 0; n < deg; n++) {
            float ex = __expf(w[n][t] - m);
            w[n][t] = ex;
            s += ex;
        }
        sinv[t] = 1.0f / s;
    }
    __syncthreads();

    // aggregate with 4 independent accumulators (MLP=4)
    const int h = t >> 3;
    float a0 = 0.f, a1 = 0.f, a2 = 0.f, a3 = 0.f;
    int n = 0;
    for (; n + 4 <= deg; n += 4) {
        a0 = fmaf(w[n + 0][h], g_g1[(size_t)cols[n + 0] * HID + t], a0);
        a1 = fmaf(w[n + 1][h], g_g1[(size_t)cols[n + 1] * HID + t], a1);
        a2 = fmaf(w[n + 2][h], g_g1[(size_t)cols[n + 2] * HID + t], a2);
        a3 = fmaf(w[n + 3][h], g_g1[(size_t)cols[n + 3] * HID + t], a3);
    }
    for (; n < deg; n++)
        a0 = fmaf(w[n][h], g_g1[(size_t)cols[n] * HID + t], a0);
    float acc = ((a0 + a1) + (a2 + a3)) * sinv[h];
    acc = (acc > 0.f) ? acc : expm1f(acc);   // ELU
    g_h[(size_t)i * HID + t] = acc;
}

// ---------------- GEMM2 + sl2/sr2: g2[N,16] = h[N,64] @ W2[64,16] --------------
// 16 rows per block, 256 threads (16 threads per row)
__global__ void gemm2(const float* __restrict__ W2,
                      const float* __restrict__ a2l, const float* __restrict__ a2r) {
    __shared__ float hs[16][64];
    __shared__ float w2s[64][CLS];
    const int tid  = threadIdx.x;
    const int row0 = blockIdx.x * 16;

    { int r = tid >> 4, c4 = tid & 15;
      *(float4*)&hs[r][c4 * 4] = *(const float4*)&g_h[(size_t)(row0 + r) * HID + c4 * 4]; }
    { int k = tid >> 2, c4 = tid & 3;
      *(float4*)&w2s[k][c4 * 4] = *(const float4*)&W2[(size_t)k * CLS + c4 * 4]; }
    __syncthreads();

    const int r = tid >> 4, c = tid & 15;
    float acc = 0.f;
    #pragma unroll
    for (int k = 0; k < HID; k++) acc = fmaf(hs[r][k], w2s[k][c], acc);
    g_g2[(size_t)(row0 + r) * CLS + c] = acc;

    float pl = acc * a2l[c];
    float pr = acc * a2r[c];
    #pragma unroll
    for (int off = 8; off >= 1; off >>= 1) {
        pl += __shfl_xor_sync(0xFFFFFFFFu, pl, off);
        pr += __shfl_xor_sync(0xFFFFFFFFu, pr, off);
    }
    if (c == 0) { g_sl2[row0 + r] = pl; g_sr2[row0 + r] = pr; }
}

// ---------------- layer-2 attention + aggregation (1 head, mean == identity) ---
// one warp per row; even/odd-neighbor parity split across half-warps for MLP
__global__ void attn2(float* __restrict__ out) {
    const int i    = blockIdx.x;
    const int lane = threadIdx.x;
    __shared__ int   cols[MAXDEG];
    __shared__ float w[MAXDEG];

    const int deg = g_deg[i];
    for (int n = lane; n < deg; n += 32) cols[n] = g_cols[(size_t)i * MAXDEG + n];
    __syncwarp();

    const float sli = g_sl2[i];
    float m = -1e30f;
    for (int n = lane; n < deg; n += 32) {
        float e = sli + g_sr2[cols[n]];
        e = fmaxf(e, 0.2f * e);
        w[n] = e;
        m = fmaxf(m, e);
    }
    #pragma unroll
    for (int off = 16; off >= 1; off >>= 1) m = fmaxf(m, __shfl_xor_sync(0xFFFFFFFFu, m, off));
    __syncwarp();

    float s = 0.f;
    for (int n = lane; n < deg; n += 32) {
        float ex = __expf(w[n] - m);
        w[n] = ex;
        s += ex;
    }
    #pragma unroll
    for (int off = 16; off >= 1; off >>= 1) s += __shfl_xor_sync(0xFFFFFFFFu, s, off);
    __syncwarp();

    const float inv = 1.0f / s;
    const int c   = lane & 15;
    const int par = lane >> 4;   // half-warp parity: lanes 0-15 even n, 16-31 odd n
    float a0 = 0.f, a1 = 0.f;
    int n = par;
    for (; n + 2 < deg; n += 4) {
        a0 = fmaf(w[n],     g_g2[(size_t)cols[n]     * CLS + c], a0);
        a1 = fmaf(w[n + 2], g_g2[(size_t)cols[n + 2] * CLS + c], a1);
    }
    for (; n < deg; n += 2)
        a0 = fmaf(w[n], g_g2[(size_t)cols[n] * CLS + c], a0);
    float acc = a0 + a1;
    acc += __shfl_xor_sync(0xFFFFFFFFu, acc, 16);
    if (par == 0) out[(size_t)i * CLS + c] = acc * inv;
}

// ---------------- launch ----------------
extern "C" void kernel_launch(void* const* d_in, const int* in_sizes, int n_in,
                              void* d_out, int out_size) {
    const float* x   = (const float*)d_in[0];
    const unsigned char* adj = (const unsigned char*)d_in[1];
    const float* W1  = (const float*)d_in[2];
    const float* a1l = (const float*)d_in[3];
    const float* a1r = (const float*)d_in[4];
    const float* W2  = (const float*)d_in[5];
    const float* a2l = (const float*)d_in[6];
    const float* a2r = (const float*)d_in[7];
    float* out = (float*)d_out;

    build_ell<<<N_NODES, 256>>>(adj);
    gemm1<<<N_NODES / 32, 128>>>(x, W1, a1l, a1r);
    attn1<<<N_NODES, 64>>>();
    gemm2<<<N_NODES / 16, 256>>>(W2, a2l, a2r);
    attn2<<<N_NODES, 32>>>(out);
}

// round 3
// speedup vs baseline: 1.6603x; 1.0627x over previous
#include <cuda_runtime.h>
#include <stdint.h>

#define N_NODES 4096
#define IN_F    512
#define HEADS   8
#define HPH     8
#define HID     64
#define CLS     16
#define MAXDEG  128
#define GEMM1_BLOCKS (N_NODES / 32)   // 128

// ---------------- scratch (static device globals; no allocation) ----------------
__device__ float g_g1[N_NODES * HID];      // layer-1 projection [N,64]
__device__ float g_sl1[N_NODES * HEADS];
__device__ float g_sr1[N_NODES * HEADS];
__device__ float g_g2[N_NODES * CLS];      // layer-2 projection
__device__ float g_sl2[N_NODES];
__device__ float g_sr2[N_NODES];
__device__ int   g_cols[N_NODES * MAXDEG]; // ELL neighbor lists
__device__ int   g_deg[N_NODES];

// =================================================================================
// K1: fused  gemm1(+sl1/sr1 epilogue)  and  build_ell.
// Blocks [0, GEMM1_BLOCKS) do the GEMM; blocks [GEMM1_BLOCKS, +N_NODES) do ELL rows.
// GEMM blocks are first so they start in wave 1 and the short ELL blocks stream
// through the remaining SM slots underneath them.
// =================================================================================
__global__ __launch_bounds__(256) void k1_ell_gemm1(
    const float* __restrict__ x, const float* __restrict__ W1,
    const float* __restrict__ a1l, const float* __restrict__ a1r,
    const unsigned char* __restrict__ adj)
{
    __shared__ union {
        struct { float As[32][36]; float Bs[32][64]; float al[HID]; float ar[HID]; } g;
        struct { int wsum[8]; int woff[9]; } e;
    } sm;

    const int tid = threadIdx.x;

    if (blockIdx.x < GEMM1_BLOCKS) {
        // ---------------- GEMM1: g1[N,64] = x[N,512] @ W1[512,64] ----------------
        // BM=32, BN=64, BK=32, 256 threads, 2x4 register tiles.
        const int m0 = blockIdx.x * 32;
        const int tx = tid & 15;   // col tile of 4
        const int ty = tid >> 4;   // row tile of 2 (16 groups * 2 rows)

        if (tid < HID) { sm.g.al[tid] = a1l[tid]; sm.g.ar[tid] = a1r[tid]; }

        float acc[2][4] = {};

        for (int k0 = 0; k0 < IN_F; k0 += 32) {
            {   // A tile: 32 rows x 32 k = 256 float4, one per thread, transposed store
                int r = tid >> 3, c4 = tid & 7;
                float4 v = *(const float4*)&x[(size_t)(m0 + r) * IN_F + k0 + c4 * 4];
                sm.g.As[c4 * 4 + 0][r] = v.x;
                sm.g.As[c4 * 4 + 1][r] = v.y;
                sm.g.As[c4 * 4 + 2][r] = v.z;
                sm.g.As[c4 * 4 + 3][r] = v.w;
            }
            #pragma unroll
            for (int it = 0; it < 2; it++) {   // B tile: 512 float4
                int idx = it * 256 + tid;
                int kk = idx >> 4, c4 = idx & 15;
                *(float4*)&sm.g.Bs[kk][c4 * 4] = *(const float4*)&W1[(size_t)(k0 + kk) * HID + c4 * 4];
            }
            __syncthreads();
            #pragma unroll
            for (int kk = 0; kk < 32; kk++) {
                float a0 = sm.g.As[kk][ty * 2 + 0];
                float a1 = sm.g.As[kk][ty * 2 + 1];
                float4 b = *(const float4*)&sm.g.Bs[kk][tx * 4];
                float bv[4] = {b.x, b.y, b.z, b.w};
                #pragma unroll
                for (int c = 0; c < 4; c++) {
                    acc[0][c] = fmaf(a0, bv[c], acc[0][c]);
                    acc[1][c] = fmaf(a1, bv[c], acc[1][c]);
                }
            }
            __syncthreads();
        }

        // store g1 + fused sl/sr epilogue (head of this col-tile = tx>>1)
        const int head = tx >> 1;
        #pragma unroll
        for (int r = 0; r < 2; r++) {
            const int row = m0 + ty * 2 + r;
            *(float4*)&g_g1[(size_t)row * HID + tx * 4] =
                make_float4(acc[r][0], acc[r][1], acc[r][2], acc[r][3]);

            float pl = 0.f, pr = 0.f;
            #pragma unroll
            for (int c = 0; c < 4; c++) {
                pl = fmaf(acc[r][c], sm.g.al[tx * 4 + c], pl);
                pr = fmaf(acc[r][c], sm.g.ar[tx * 4 + c], pr);
            }
            pl += __shfl_xor_sync(0xFFFFFFFFu, pl, 1);
            pr += __shfl_xor_sync(0xFFFFFFFFu, pr, 1);
            if (!(tx & 1)) {
                g_sl1[row * HEADS + head] = pl;
                g_sr1[row * HEADS + head] = pr;
            }
        }
        return;
    }

    // ---------------- build_ell: one block per row, warp-shuffle scan ------------
    // dtype probe: byte[3]==0x3F -> float32; byte[4097]==1 -> bool; else int32
    const int i    = blockIdx.x - GEMM1_BLOCKS;
    const int lane = tid & 31;
    const int wid  = tid >> 5;

    int dt;
    if (adj[3] == 0x3Fu)        dt = 1;
    else if (adj[4097] == 1u)   dt = 0;
    else                        dt = 2;

    uint32_t vb[4];
    float4   vf[4];
    int4     vi[4];
    int cnt = 0;
    if (dt == 0) {
        const uint4 u = *((const uint4*)(adj + (size_t)i * N_NODES) + tid);
        vb[0] = u.x; vb[1] = u.y; vb[2] = u.z; vb[3] = u.w;
        #pragma unroll
        for (int k = 0; k < 4; k++) {
            uint32_t v = vb[k];
            if (v) {
                cnt += ((v       & 0xFFu) != 0) + (((v >> 8)  & 0xFFu) != 0)
                     + (((v >> 16) & 0xFFu) != 0) + (((v >> 24) & 0xFFu) != 0);
            }
        }
    } else if (dt == 1) {
        const float4* p = (const float4*)(adj) + (size_t)i * (N_NODES / 4) + tid * 4;
        #pragma unroll
        for (int k = 0; k < 4; k++) {
            vf[k] = p[k];
            cnt += (vf[k].x != 0.f) + (vf[k].y != 0.f) + (vf[k].z != 0.f) + (vf[k].w != 0.f);
        }
    } else {
        const int4* p = (const int4*)(adj) + (size_t)i * (N_NODES / 4) + tid * 4;
        #pragma unroll
        for (int k = 0; k < 4; k++) {
            vi[k] = p[k];
            cnt += (vi[k].x != 0) + (vi[k].y != 0) + (vi[k].z != 0) + (vi[k].w != 0);
        }
    }

    int incl = cnt;
    #pragma unroll
    for (int off = 1; off < 32; off <<= 1) {
        int v = __shfl_up_sync(0xFFFFFFFFu, incl, off);
        if (lane >= off) incl += v;
    }
    if (lane == 31) sm.e.wsum[wid] = incl;
    __syncthreads();
    if (tid == 0) {
        int s = 0;
        #pragma unroll
        for (int w = 0; w < 8; w++) { sm.e.woff[w] = s; s += sm.e.wsum[w]; }
        sm.e.woff[8] = s;
    }
    __syncthreads();

    int pos = sm.e.woff[wid] + (incl - cnt);
    const int total = sm.e.woff[8];

    const int j0 = tid * 16;
    int* dst = &g_cols[(size_t)i * MAXDEG];
    if (dt == 0) {
        #pragma unroll
        for (int k = 0; k < 4; k++) {
            uint32_t v = vb[k];
            #pragma unroll
            for (int b = 0; b < 4; b++)
                if ((v >> (8 * b)) & 0xFFu) { if (pos < MAXDEG) dst[pos] = j0 + k * 4 + b; pos++; }
        }
    } else if (dt == 1) {
        #pragma unroll
        for (int k = 0; k < 4; k++) {
            float e[4] = {vf[k].x, vf[k].y, vf[k].z, vf[k].w};
            #pragma unroll
            for (int b = 0; b < 4; b++)
                if (e[b] != 0.f) { if (pos < MAXDEG) dst[pos] = j0 + k * 4 + b; pos++; }
        }
    } else {
        #pragma unroll
        for (int k = 0; k < 4; k++) {
            int e[4] = {vi[k].x, vi[k].y, vi[k].z, vi[k].w};
            #pragma unroll
            for (int b = 0; b < 4; b++)
                if (e[b] != 0) { if (pos < MAXDEG) dst[pos] = j0 + k * 4 + b; pos++; }
        }
    }
    if (tid == 0) g_deg[i] = min(total, MAXDEG);
}

// =================================================================================
// K2: layer-1 attention + aggregation + ELU, fused with gemm2 (+sl2/sr2 epilogue).
// One block (64 threads) per row i; thread t owns feature t = h*8+d.
// =================================================================================
__global__ __launch_bounds__(64) void k2_attn1_gemm2(
    const float* __restrict__ W2,
    const float* __restrict__ a2l, const float* __restrict__ a2r)
{
    const int i = blockIdx.x;
    const int t = threadIdx.x;
    __shared__ int   cols[MAXDEG];
    __shared__ float w[MAXDEG][HEADS];
    __shared__ float sinv[HEADS];
    __shared__ float W2s[HID * CLS];   // 1024 floats
    __shared__ float hs[HID];
    __shared__ float part[4][CLS];

    // preload W2 (hidden under the neighbor-list / score gathers)
    #pragma unroll
    for (int it = 0; it < 4; it++)
        ((float4*)W2s)[it * 64 + t] = ((const float4*)W2)[it * 64 + t];

    const int deg = g_deg[i];
    for (int n = t; n < deg; n += 64) cols[n] = g_cols[(size_t)i * MAXDEG + n];
    __syncthreads();

    // scores: e = leaky_relu(sl[i,h] + sr[j,h])
    for (int idx = t; idx < deg * HEADS; idx += 64) {
        int n = idx >> 3, h = idx & 7;
        float e = g_sl1[i * HEADS + h] + g_sr1[cols[n] * HEADS + h];
        w[n][h] = fmaxf(e, 0.2f * e);
    }
    __syncthreads();

    // per-head softmax (deg ~17)
    if (t < HEADS) {
        float m = -1e30f;
        for (int n = 0; n < deg; n++) m = fmaxf(m, w[n][t]);
        float s = 0.f;
        for (int n = 0; n < deg; n++) {
            float ex = __expf(w[n][t] - m);
            w[n][t] = ex;
            s += ex;
        }
        sinv[t] = 1.0f / s;
    }
    __syncthreads();

    // aggregate with 4 independent accumulators (MLP=4)
    const int h = t >> 3;
    float a0 = 0.f, a1 = 0.f, a2 = 0.f, a3 = 0.f;
    int n = 0;
    for (; n + 4 <= deg; n += 4) {
        a0 = fmaf(w[n + 0][h], g_g1[(size_t)cols[n + 0] * HID + t], a0);
        a1 = fmaf(w[n + 1][h], g_g1[(size_t)cols[n + 1] * HID + t], a1);
        a2 = fmaf(w[n + 2][h], g_g1[(size_t)cols[n + 2] * HID + t], a2);
        a3 = fmaf(w[n + 3][h], g_g1[(size_t)cols[n + 3] * HID + t], a3);
    }
    for (; n < deg; n++)
        a0 = fmaf(w[n][h], g_g1[(size_t)cols[n] * HID + t], a0);
    float acc = ((a0 + a1) + (a2 + a3)) * sinv[h];
    acc = (acc > 0.f) ? acc : expm1f(acc);   // ELU
    hs[t] = acc;                             // h row stays in shared, never to HBM
    __syncthreads();

    // fused gemm2: g2[i,c] = sum_k hs[k] * W2[k,c]; 4 partials of 16 k each
    {
        const int c  = t & 15;
        const int kg = (t >> 4) * 16;
        float p = 0.f;
        #pragma unroll
        for (int k = 0; k < 16; k++)
            p = fmaf(hs[kg + k], W2s[(kg + k) * CLS + c], p);
        part[t >> 4][c] = p;
    }
    __syncthreads();

    if (t < CLS) {
        float g2v = ((part[0][t] + part[1][t]) + (part[2][t] + part[3][t]));
        g_g2[(size_t)i * CLS + t] = g2v;
        float pl = g2v * a2l[t];
        float pr = g2v * a2r[t];
        #pragma unroll
        for (int off = 8; off >= 1; off >>= 1) {
            pl += __shfl_xor_sync(0xFFFFu, pl, off);
            pr += __shfl_xor_sync(0xFFFFu, pr, off);
        }
        if (t == 0) { g_sl2[i] = pl; g_sr2[i] = pr; }
    }
}

// =================================================================================
// K3: layer-2 attention + aggregation (1 head, mean over 1 head == identity).
// One warp per row; even/odd-neighbor parity split across half-warps for MLP.
// =================================================================================
__global__ __launch_bounds__(32) void k3_attn2(float* __restrict__ out) {
    const int i    = blockIdx.x;
    const int lane = threadIdx.x;
    __shared__ int   cols[MAXDEG];
    __shared__ float w[MAXDEG];

    const int deg = g_deg[i];
    for (int n = lane; n < deg; n += 32) cols[n] = g_cols[(size_t)i * MAXDEG + n];
    __syncwarp();

    const float sli = g_sl2[i];
    float m = -1e30f;
    for (int n = lane; n < deg; n += 32) {
        float e = sli + g_sr2[cols[n]];
        e = fmaxf(e, 0.2f * e);
        w[n] = e;
        m = fmaxf(m, e);
    }
    #pragma unroll
    for (int off = 16; off >= 1; off >>= 1) m = fmaxf(m, __shfl_xor_sync(0xFFFFFFFFu, m, off));
    __syncwarp();

    float s = 0.f;
    for (int n = lane; n < deg; n += 32) {
        float ex = __expf(w[n] - m);
        w[n] = ex;
        s += ex;
    }
    #pragma unroll
    for (int off = 16; off >= 1; off >>= 1) s += __shfl_xor_sync(0xFFFFFFFFu, s, off);
    __syncwarp();

    const float inv = 1.0f / s;
    const int c   = lane & 15;
    const int par = lane >> 4;
    float a0 = 0.f, a1 = 0.f;
    int n = par;
    for (; n + 2 < deg; n += 4) {
        a0 = fmaf(w[n],     g_g2[(size_t)cols[n]     * CLS + c], a0);
        a1 = fmaf(w[n + 2], g_g2[(size_t)cols[n + 2] * CLS + c], a1);
    }
    for (; n < deg; n += 2)
        a0 = fmaf(w[n], g_g2[(size_t)cols[n] * CLS + c], a0);
    float acc = a0 + a1;
    acc += __shfl_xor_sync(0xFFFFFFFFu, acc, 16);
    if (par == 0) out[(size_t)i * CLS + c] = acc * inv;
}

// ---------------- launch ----------------
extern "C" void kernel_launch(void* const* d_in, const int* in_sizes, int n_in,
                              void* d_out, int out_size) {
    const float* x   = (const float*)d_in[0];
    const unsigned char* adj = (const unsigned char*)d_in[1];
    const float* W1  = (const float*)d_in[2];
    const float* a1l = (const float*)d_in[3];
    const float* a1r = (const float*)d_in[4];
    const float* W2  = (const float*)d_in[5];
    const float* a2l = (const float*)d_in[6];
    const float* a2r = (const float*)d_in[7];
    float* out = (float*)d_out;

    k1_ell_gemm1<<<GEMM1_BLOCKS + N_NODES, 256>>>(x, W1, a1l, a1r, adj);
    k2_attn1_gemm2<<<N_NODES, 64>>>(W2, a2l, a2r);
    k3_attn2<<<N_NODES, 32>>>(out);
}